// round 14
// baseline (speedup 1.0000x reference)
#include <cuda_runtime.h>

#define K_CODES 16384
#define N_ROWS  8192
#define CAP     1024
#define TK      256            // warm-pass tile
#define PROBES  1024
#define BT      64             // sweep block threads
#define CPT     4              // codes per thread (sweep)
#define CPB     (BT * CPT)     // codes per block = 256
#define RSPLIT  16
#define RPB     (N_ROWS / RSPLIT)   // 512 rows per block
#define NPAIR   (RPB / 2)           // 256 row-pairs

// ---------------- scratch (__device__ globals: no allocs allowed) -------------
__device__ float g_cbp[9 * K_CODES];     // SoA: j<8 -> -2*e_j[k]; j==8 -> sum e^2
__device__ float g_warm[N_ROWS];
__device__ int   g_cnt[N_ROWS];
__device__ int2  g_cand[N_ROWS * CAP];
__device__ float g_avg[K_CODES];
__device__ float g_sampleH;
__device__ float g_mse;

// ---------------- helpers -----------------------------------------------------
static __device__ __forceinline__ unsigned long long pk2(float a, float b) {
    unsigned long long r;
    asm("mov.b64 %0, {%1, %2};" : "=l"(r) : "f"(a), "f"(b));
    return r;
}
static __device__ __forceinline__ void upk2(unsigned long long v, float& a, float& b) {
    asm("mov.b64 {%0, %1}, %2;" : "=f"(a), "=f"(b) : "l"(v));
}
static __device__ __forceinline__ unsigned long long ffma2(
    unsigned long long a, unsigned long long b, unsigned long long c) {
    unsigned long long d;
    asm("fma.rn.f32x2 %0, %1, %2, %3;" : "=l"(d) : "l"(a), "l"(b), "l"(c));
    return d;
}
static __device__ __forceinline__ unsigned long long add2(
    unsigned long long a, unsigned long long b) {
    unsigned long long d;
    asm("add.rn.f32x2 %0, %1, %2;" : "=l"(d) : "l"(a), "l"(b));
    return d;
}
static __device__ __forceinline__ unsigned hi32(unsigned long long v) {
    return (unsigned)(v >> 32);
}
static __device__ __forceinline__ unsigned lo32(unsigned long long v) {
    return (unsigned)v;
}

// ---------------- pass 0: zero scratch + preprocess codebook ------------------
__global__ void k_init(const float* __restrict__ cb) {
    int t = blockIdx.x * 256 + threadIdx.x;       // grid 64 -> t < 16384
    if (t < N_ROWS) g_cnt[t] = 0;
    if (t == 0) { g_sampleH = 0.f; g_mse = 0.f; }
    if (t < K_CODES) {
        g_avg[t] = 0.f;
        float ss = 0.f;
#pragma unroll
        for (int j = 0; j < 8; j++) {
            float e = cb[t * 8 + j];
            g_cbp[j * K_CODES + t] = -2.f * e;
            ss += e * e;
        }
        g_cbp[8 * K_CODES + t] = ss;
    }
}

// ---------------- pass 1: warm-start min over first PROBES codes --------------
__global__ __launch_bounds__(256, 2) void k_warm(const float* __restrict__ z) {
    __shared__ __align__(16) float s_cb[9][2 * TK];
    __shared__ float s_z[64 * 8];

    const int tid  = threadIdx.x;
    const int lane = tid & 31;
    const int w    = tid >> 5;
    const int rowBase = blockIdx.x * 64;

    for (int i = tid; i < 512; i += 256) {
        int ro = i >> 3, j = i & 7;
        int row = rowBase + ro;
        s_z[i] = z[(row >> 8) * 2048 + j * 256 + (row & 255)];
    }
    __syncthreads();

    unsigned long long z2[4][8];
#pragma unroll
    for (int p = 0; p < 4; p++)
#pragma unroll
        for (int j = 0; j < 8; j++)
            z2[p][j] = pk2(s_z[(w * 8 + 2 * p) * 8 + j],
                           s_z[(w * 8 + 2 * p + 1) * 8 + j]);

    float dmin[8];
#pragma unroll
    for (int r = 0; r < 8; r++) dmin[r] = 3.4e38f;

    for (int tile = 0; tile < PROBES / TK; ++tile) {
        __syncthreads();
#pragma unroll
        for (int j = 0; j < 9; j++) {
            float v = g_cbp[j * K_CODES + tile * TK + tid];
            ((float2*)s_cb[j])[tid] = make_float2(v, v);
        }
        __syncthreads();
#pragma unroll 2
        for (int s = 0; s < TK / 32; s++) {
            int off = (s * 32 + lane) * 2;
            unsigned long long ee2 = *(const unsigned long long*)&s_cb[8][off];
            unsigned long long a0 = ee2, a1 = ee2, a2 = ee2, a3 = ee2;
#pragma unroll
            for (int j = 0; j < 8; j++) {
                unsigned long long ej = *(const unsigned long long*)&s_cb[j][off];
                a0 = ffma2(z2[0][j], ej, a0);
                a1 = ffma2(z2[1][j], ej, a1);
                a2 = ffma2(z2[2][j], ej, a2);
                a3 = ffma2(z2[3][j], ej, a3);
            }
            float d[8];
            upk2(a0, d[0], d[1]); upk2(a1, d[2], d[3]);
            upk2(a2, d[4], d[5]); upk2(a3, d[6], d[7]);
#pragma unroll
            for (int r = 0; r < 8; r++) dmin[r] = fminf(dmin[r], d[r]);
        }
    }
#pragma unroll
    for (int r = 0; r < 8; r++) {
        float v = dmin[r];
        for (int o = 16; o; o >>= 1)
            v = fminf(v, __shfl_xor_sync(0xffffffffu, v, o));
        if (lane == 0) g_warm[rowBase + w * 8 + r] = v;
    }
}

// ---------------- dummy launch so ncu profiles k_sweep as launch #4 -----------
__global__ void k_nop() {}

// ---------------- pass 2: code-resident sweep, 4 codes/thread, 4 chains -------
// grid (64 codeblocks, 16 rowsplits) x 64 thr
__global__ __launch_bounds__(BT, 8) void k_sweep(const float* __restrict__ z) {
    __shared__ __align__(16) float s_zp[NPAIR * 16];            // 16KB row-pair packed
    __shared__ __align__(16) unsigned long long s_ncut[NPAIR];  // 2KB

    const int tid  = threadIdx.x;
    const int rowBase = blockIdx.y * RPB;
    const int kbase   = blockIdx.x * CPB + tid;   // codes: kbase + {0,64,128,192}

    // stage z rows, coalesced: j outer, consecutive rows inner
#pragma unroll
    for (int i = 0; i < 64; i++) {                // 8 j x 8 row-chunks of 64
        int j  = i >> 3;
        int ro = (i & 7) * BT + tid;
        int row = rowBase + ro;
        s_zp[(ro >> 1) * 16 + j * 2 + (ro & 1)] =
            z[(row >> 8) * 2048 + j * 256 + (row & 255)];
    }
    // stage negated cuts per row-pair (4 per thread)
#pragma unroll
    for (int u = 0; u < NPAIR / BT; u++) {
        int rp = u * BT + tid;
        int r0 = rowBase + 2 * rp;
        // cut = warm + 0.88: exp(-100*0.88) underflows fp32 (matches ref zeros)
        s_ncut[rp] = pk2(-(g_warm[r0] + 0.88f), -(g_warm[r0 + 1] + 0.88f));
    }

    // codebooks for this thread's 4 codes -> registers (dup-packed for f32x2)
    unsigned long long vd[CPT][8], ee[CPT];
#pragma unroll
    for (int c = 0; c < CPT; c++) {
#pragma unroll
        for (int j = 0; j < 8; j++) {
            float v = g_cbp[j * K_CODES + kbase + c * BT];
            vd[c][j] = pk2(v, v);
        }
        float ss = g_cbp[8 * K_CODES + kbase + c * BT];
        ee[c] = pk2(ss, ss);
    }
    __syncthreads();

#pragma unroll 4
    for (int rp = 0; rp < NPAIR; rp++) {
        const ulonglong2* zp = (const ulonglong2*)&s_zp[rp * 16]; // broadcast
        ulonglong2 p0 = zp[0], p1 = zp[1], p2 = zp[2], p3 = zp[3];
        unsigned long long nc = s_ncut[rp];
        unsigned long long a0 = add2(ee[0], nc);
        unsigned long long a1 = add2(ee[1], nc);
        unsigned long long a2 = add2(ee[2], nc);
        unsigned long long a3 = add2(ee[3], nc);
        a0 = ffma2(p0.x, vd[0][0], a0); a1 = ffma2(p0.x, vd[1][0], a1);
        a2 = ffma2(p0.x, vd[2][0], a2); a3 = ffma2(p0.x, vd[3][0], a3);
        a0 = ffma2(p0.y, vd[0][1], a0); a1 = ffma2(p0.y, vd[1][1], a1);
        a2 = ffma2(p0.y, vd[2][1], a2); a3 = ffma2(p0.y, vd[3][1], a3);
        a0 = ffma2(p1.x, vd[0][2], a0); a1 = ffma2(p1.x, vd[1][2], a1);
        a2 = ffma2(p1.x, vd[2][2], a2); a3 = ffma2(p1.x, vd[3][2], a3);
        a0 = ffma2(p1.y, vd[0][3], a0); a1 = ffma2(p1.y, vd[1][3], a1);
        a2 = ffma2(p1.y, vd[2][3], a2); a3 = ffma2(p1.y, vd[3][3], a3);
        a0 = ffma2(p2.x, vd[0][4], a0); a1 = ffma2(p2.x, vd[1][4], a1);
        a2 = ffma2(p2.x, vd[2][4], a2); a3 = ffma2(p2.x, vd[3][4], a3);
        a0 = ffma2(p2.y, vd[0][5], a0); a1 = ffma2(p2.y, vd[1][5], a1);
        a2 = ffma2(p2.y, vd[2][5], a2); a3 = ffma2(p2.y, vd[3][5], a3);
        a0 = ffma2(p3.x, vd[0][6], a0); a1 = ffma2(p3.x, vd[1][6], a1);
        a2 = ffma2(p3.x, vd[2][6], a2); a3 = ffma2(p3.x, vd[3][6], a3);
        a0 = ffma2(p3.y, vd[0][7], a0); a1 = ffma2(p3.y, vd[1][7], a1);
        a2 = ffma2(p3.y, vd[2][7], a2); a3 = ffma2(p3.y, vd[3][7], a3);
        unsigned acc = (lo32(a0) | hi32(a0)) | (lo32(a1) | hi32(a1));
        acc |= (lo32(a2) | hi32(a2)) | (lo32(a3) | hi32(a3));
        // hit iff any sign bit set; results still live (no recompute)
        if ((int)acc < 0) {
            int row0 = rowBase + 2 * rp, row1 = row0 + 1;
            unsigned long long as[4] = {a0, a1, a2, a3};
#pragma unroll
            for (int c = 0; c < CPT; c++) {
                float dlo, dhi;
                upk2(as[c], dlo, dhi);
                int k = kbase + c * BT;
                if (dlo < 0.f) {
                    int pos = atomicAdd(&g_cnt[row0], 1);
                    if (pos < CAP)
                        g_cand[row0 * CAP + pos] = make_int2(k, __float_as_int(dlo));
                }
                if (dhi < 0.f) {
                    int pos = atomicAdd(&g_cnt[row1], 1);
                    if (pos < CAP)
                        g_cand[row1 * CAP + pos] = make_int2(k, __float_as_int(dhi));
                }
            }
        }
    }
}

// ---------------- pass 3: per-row finalize, block-reduced scalars -------------
// note: stored d's are shifted by -cut[row] (row-uniform) -> differences exact
// grid 1024 x 256 thr, 8 rows per block (grid exact: no early return)
__global__ void k_finalize(const float* __restrict__ z,
                           const float* __restrict__ cb,
                           float* __restrict__ out) {
    __shared__ float s_mse[8], s_H[8];
    __shared__ float s_idx[8];

    int tid  = threadIdx.x;
    int wid  = tid >> 5;
    int lane = tid & 31;
    int gw   = blockIdx.x * 8 + wid;               // row for this warp

    int cnt = min(g_cnt[gw], CAP);

    float dmin = 1e30f, S1 = 0.f, S2 = 0.f;
    int   idx  = 0x7fffffff;
    for (int i = lane; i < cnt; i += 32) {
        int2 c = g_cand[gw * CAP + i];
        float d = __int_as_float(c.y);
        if (d < dmin) {
            float delta = -100.f * (dmin - d);
            float sc = __expf(delta);
            S2 = sc * (S2 + delta * S1);
            S1 = sc * S1 + 1.f;
            dmin = d; idx = c.x;
        } else {
            float arg = -100.f * (d - dmin);
            float e = __expf(arg);
            S1 += e; S2 += e * arg;
            if (d == dmin) idx = min(idx, c.x);
        }
    }
    for (int o = 16; o; o >>= 1) {
        float od  = __shfl_xor_sync(0xffffffffu, dmin, o);
        float oS1 = __shfl_xor_sync(0xffffffffu, S1, o);
        float oS2 = __shfl_xor_sync(0xffffffffu, S2, o);
        int   oix = __shfl_xor_sync(0xffffffffu, idx, o);
        float dlo = fminf(dmin, od);
        float da = -100.f * (dmin - dlo); float sa = __expf(da);
        float db = -100.f * (od  - dlo);  float sb = __expf(db);
        float nS2 = sa * (S2 + da * S1) + sb * (oS2 + db * oS1);
        float nS1 = sa * S1 + sb * oS1;
        int nidx;
        if (od < dmin)       nidx = oix;
        else if (od == dmin) nidx = min(idx, oix);
        else                 nidx = idx;
        dmin = dlo; S1 = nS1; S2 = nS2; idx = nidx;
    }

    float inv = 1.0f / (S1 * 8192.0f);
    for (int i = lane; i < cnt; i += 32) {
        int2 c = g_cand[gw * CAP + i];
        float e = __expf(-100.f * (__int_as_float(c.y) - dmin));
        if (e > 0.f) atomicAdd(&g_avg[c.x], e * inv);
    }

    int b = gw >> 8, rem = gw & 255;
    float local = 0.f;
    if (lane < 8) {
        float q  = cb[idx * 8 + lane];
        float zv = z[b * 2048 + lane * 256 + rem];
        out[b * 2048 + lane * 256 + rem] = q;       // z_q (straight-through fwd)
        float df = q - zv;
        local = df * df;
    }
    local += __shfl_xor_sync(0xffffffffu, local, 1);
    local += __shfl_xor_sync(0xffffffffu, local, 2);
    local += __shfl_xor_sync(0xffffffffu, local, 4);
    if (lane == 0) {
        s_mse[wid] = local;
        s_H[wid]   = S2 / S1 - logf(S1);           // = sum p*logp for this row
        s_idx[wid] = (float)idx;
    }
    __syncthreads();
    if (tid < 8)                                    // coalesced idx write (32B)
        out[65537 + blockIdx.x * 8 + tid] = s_idx[tid];
    if (tid == 0) {
        float m = 0.f, h = 0.f;
#pragma unroll
        for (int i = 0; i < 8; i++) { m += s_mse[i]; h += s_H[i]; }
        atomicAdd(&g_mse, m);                       // 1024 atomics, not 8192
        atomicAdd(&g_sampleH, h);
    }
}

// ---------------- pass 4: avg-entropy reduce + loss ---------------------------
__global__ void k_final(float* __restrict__ out) {
    __shared__ float red[256];
    float a = 0.f;
    for (int k = threadIdx.x; k < K_CODES; k += 256) {
        float av = g_avg[k];
        a += av * logf(av + 1e-5f);
    }
    red[threadIdx.x] = a;
    __syncthreads();
    for (int s = 128; s; s >>= 1) {
        if (threadIdx.x < s) red[threadIdx.x] += red[threadIdx.x + s];
        __syncthreads();
    }
    if (threadIdx.x == 0) {
        float sample_entropy = -(g_sampleH / 8192.0f);
        float ent = 0.1f * (sample_entropy + red[0]);
        out[65536] = 1.25f * g_mse / 65536.0f + ent;
    }
}

// ---------------- launch ------------------------------------------------------
extern "C" void kernel_launch(void* const* d_in, const int* in_sizes, int n_in,
                              void* d_out, int out_size) {
    const float* z  = (const float*)d_in[0];
    const float* cb = (const float*)d_in[1];
    float* out = (float*)d_out;
    (void)in_sizes; (void)n_in; (void)out_size;

    k_init<<<64, 256>>>(cb);
    k_warm<<<128, 256>>>(z);
    k_nop<<<1, 32>>>();                       // keeps k_sweep as ncu's profiled launch
    k_sweep<<<dim3(K_CODES / CPB, RSPLIT), BT>>>(z);
    k_finalize<<<1024, 256>>>(z, cb, out);
    k_final<<<1, 256>>>(out);
}

// round 15
// speedup vs baseline: 1.7097x; 1.7097x over previous
#include <cuda_runtime.h>

#define K_CODES 16384
#define N_ROWS  8192
#define CAP     1024
#define TK      256            // warm-pass tile
#define PROBES  1024
#define BT      128            // sweep block threads
#define CPT     2              // codes per thread (sweep)
#define CPB     (BT * CPT)     // codes per block = 256
#define RSPLIT  32
#define RPB     (N_ROWS / RSPLIT)   // 256 rows per block
#define NPAIR   (RPB / 2)           // 128 row-pairs

// ---------------- scratch (__device__ globals: no allocs allowed) -------------
__device__ float g_cbp[9 * K_CODES];     // SoA: j<8 -> -2*e_j[k]; j==8 -> sum e^2
__device__ float g_warm[N_ROWS];
__device__ int   g_cnt[N_ROWS];
__device__ int2  g_cand[N_ROWS * CAP];
__device__ float g_avg[K_CODES];
__device__ float g_sampleH;
__device__ float g_mse;

// ---------------- helpers -----------------------------------------------------
static __device__ __forceinline__ unsigned long long pk2(float a, float b) {
    unsigned long long r;
    asm("mov.b64 %0, {%1, %2};" : "=l"(r) : "f"(a), "f"(b));
    return r;
}
static __device__ __forceinline__ void upk2(unsigned long long v, float& a, float& b) {
    asm("mov.b64 {%0, %1}, %2;" : "=f"(a), "=f"(b) : "l"(v));
}
static __device__ __forceinline__ unsigned long long ffma2(
    unsigned long long a, unsigned long long b, unsigned long long c) {
    unsigned long long d;
    asm("fma.rn.f32x2 %0, %1, %2, %3;" : "=l"(d) : "l"(a), "l"(b), "l"(c));
    return d;
}
static __device__ __forceinline__ unsigned long long add2(
    unsigned long long a, unsigned long long b) {
    unsigned long long d;
    asm("add.rn.f32x2 %0, %1, %2;" : "=l"(d) : "l"(a), "l"(b));
    return d;
}
static __device__ __forceinline__ unsigned hi32(unsigned long long v) {
    return (unsigned)(v >> 32);
}
static __device__ __forceinline__ unsigned lo32(unsigned long long v) {
    return (unsigned)v;
}

// ---------------- pass 0: zero scratch + preprocess codebook ------------------
__global__ void k_init(const float* __restrict__ cb) {
    int t = blockIdx.x * 256 + threadIdx.x;       // grid 64 -> t < 16384
    if (t < N_ROWS) g_cnt[t] = 0;
    if (t == 0) { g_sampleH = 0.f; g_mse = 0.f; }
    if (t < K_CODES) {
        g_avg[t] = 0.f;
        float ss = 0.f;
#pragma unroll
        for (int j = 0; j < 8; j++) {
            float e = cb[t * 8 + j];
            g_cbp[j * K_CODES + t] = -2.f * e;
            ss += e * e;
        }
        g_cbp[8 * K_CODES + t] = ss;
    }
}

// ---------------- pass 1: warm-start min over first PROBES codes --------------
__global__ __launch_bounds__(256, 2) void k_warm(const float* __restrict__ z) {
    __shared__ __align__(16) float s_cb[9][2 * TK];
    __shared__ float s_z[64 * 8];

    const int tid  = threadIdx.x;
    const int lane = tid & 31;
    const int w    = tid >> 5;
    const int rowBase = blockIdx.x * 64;

    for (int i = tid; i < 512; i += 256) {
        int ro = i >> 3, j = i & 7;
        int row = rowBase + ro;
        s_z[i] = z[(row >> 8) * 2048 + j * 256 + (row & 255)];
    }
    __syncthreads();

    unsigned long long z2[4][8];
#pragma unroll
    for (int p = 0; p < 4; p++)
#pragma unroll
        for (int j = 0; j < 8; j++)
            z2[p][j] = pk2(s_z[(w * 8 + 2 * p) * 8 + j],
                           s_z[(w * 8 + 2 * p + 1) * 8 + j]);

    float dmin[8];
#pragma unroll
    for (int r = 0; r < 8; r++) dmin[r] = 3.4e38f;

    for (int tile = 0; tile < PROBES / TK; ++tile) {
        __syncthreads();
#pragma unroll
        for (int j = 0; j < 9; j++) {
            float v = g_cbp[j * K_CODES + tile * TK + tid];
            ((float2*)s_cb[j])[tid] = make_float2(v, v);
        }
        __syncthreads();
#pragma unroll 2
        for (int s = 0; s < TK / 32; s++) {
            int off = (s * 32 + lane) * 2;
            unsigned long long ee2 = *(const unsigned long long*)&s_cb[8][off];
            unsigned long long a0 = ee2, a1 = ee2, a2 = ee2, a3 = ee2;
#pragma unroll
            for (int j = 0; j < 8; j++) {
                unsigned long long ej = *(const unsigned long long*)&s_cb[j][off];
                a0 = ffma2(z2[0][j], ej, a0);
                a1 = ffma2(z2[1][j], ej, a1);
                a2 = ffma2(z2[2][j], ej, a2);
                a3 = ffma2(z2[3][j], ej, a3);
            }
            float d[8];
            upk2(a0, d[0], d[1]); upk2(a1, d[2], d[3]);
            upk2(a2, d[4], d[5]); upk2(a3, d[6], d[7]);
#pragma unroll
            for (int r = 0; r < 8; r++) dmin[r] = fminf(dmin[r], d[r]);
        }
    }
#pragma unroll
    for (int r = 0; r < 8; r++) {
        float v = dmin[r];
        for (int o = 16; o; o >>= 1)
            v = fminf(v, __shfl_xor_sync(0xffffffffu, v, o));
        if (lane == 0) g_warm[rowBase + w * 8 + r] = v;
    }
}

// ---------------- dummy launch so ncu profiles k_sweep as launch #4 -----------
__global__ void k_nop() {}

// ---------------- pass 2: code-resident sweep, per-iter sign check ------------
// grid (64 codeblocks, 32 rowsplits) x 128 thr, 8 blocks/SM fully resident
__global__ __launch_bounds__(BT, 8) void k_sweep(const float* __restrict__ z) {
    __shared__ __align__(16) float s_zp[NPAIR * 16];            // 8KB row-pair packed
    __shared__ __align__(16) unsigned long long s_ncut[NPAIR];  // 1KB

    const int tid  = threadIdx.x;
    const int rowBase = blockIdx.y * RPB;
    const int kbase   = blockIdx.x * CPB + tid;   // codes: kbase, kbase+BT

    // stage z rows, coalesced: j outer, consecutive rows inner
#pragma unroll
    for (int i = 0; i < 16; i++) {                // 8 j x 2 row-chunks of 128
        int j  = i >> 1;
        int ro = (i & 1) * BT + tid;
        int row = rowBase + ro;
        s_zp[(ro >> 1) * 16 + j * 2 + (ro & 1)] =
            z[(row >> 8) * 2048 + j * 256 + (row & 255)];
    }
    // stage negated cuts per row-pair (1 per thread)
    {
        int rp = tid;
        int r0 = rowBase + 2 * rp;
        // cut = warm + 0.88: exp(-100*0.88) underflows fp32 (matches ref zeros)
        s_ncut[rp] = pk2(-(g_warm[r0] + 0.88f), -(g_warm[r0 + 1] + 0.88f));
    }

    // codebooks for this thread's 2 codes -> registers (dup-packed for f32x2)
    unsigned long long vd0[8], vd1[8], ee0, ee1;
#pragma unroll
    for (int j = 0; j < 8; j++) {
        float v0 = g_cbp[j * K_CODES + kbase];
        float v1 = g_cbp[j * K_CODES + kbase + BT];
        vd0[j] = pk2(v0, v0);
        vd1[j] = pk2(v1, v1);
    }
    {
        float s0 = g_cbp[8 * K_CODES + kbase];
        float s1 = g_cbp[8 * K_CODES + kbase + BT];
        ee0 = pk2(s0, s0);
        ee1 = pk2(s1, s1);
    }
    __syncthreads();

#pragma unroll 4
    for (int rp = 0; rp < NPAIR; rp++) {
        const ulonglong2* zp = (const ulonglong2*)&s_zp[rp * 16]; // broadcast
        ulonglong2 p0 = zp[0], p1 = zp[1], p2 = zp[2], p3 = zp[3];
        unsigned long long nc = s_ncut[rp];
        unsigned long long a0 = add2(ee0, nc);
        unsigned long long a1 = add2(ee1, nc);
        a0 = ffma2(p0.x, vd0[0], a0);  a1 = ffma2(p0.x, vd1[0], a1);
        a0 = ffma2(p0.y, vd0[1], a0);  a1 = ffma2(p0.y, vd1[1], a1);
        a0 = ffma2(p1.x, vd0[2], a0);  a1 = ffma2(p1.x, vd1[2], a1);
        a0 = ffma2(p1.y, vd0[3], a0);  a1 = ffma2(p1.y, vd1[3], a1);
        a0 = ffma2(p2.x, vd0[4], a0);  a1 = ffma2(p2.x, vd1[4], a1);
        a0 = ffma2(p2.y, vd0[5], a0);  a1 = ffma2(p2.y, vd1[5], a1);
        a0 = ffma2(p3.x, vd0[6], a0);  a1 = ffma2(p3.x, vd1[6], a1);
        a0 = ffma2(p3.y, vd0[7], a0);  a1 = ffma2(p3.y, vd1[7], a1);
        unsigned acc = (lo32(a0) | hi32(a0)) | (lo32(a1) | hi32(a1));
        // hit iff any sign bit set; results still live in a0/a1 (no recompute)
        if ((int)acc < 0) {
            float d00, d01, d10, d11;
            upk2(a0, d00, d01);
            upk2(a1, d10, d11);
            int row0 = rowBase + 2 * rp, row1 = row0 + 1;
            if (d00 < 0.f) {
                int pos = atomicAdd(&g_cnt[row0], 1);
                if (pos < CAP)
                    g_cand[row0 * CAP + pos] = make_int2(kbase, __float_as_int(d00));
            }
            if (d01 < 0.f) {
                int pos = atomicAdd(&g_cnt[row1], 1);
                if (pos < CAP)
                    g_cand[row1 * CAP + pos] = make_int2(kbase, __float_as_int(d01));
            }
            if (d10 < 0.f) {
                int pos = atomicAdd(&g_cnt[row0], 1);
                if (pos < CAP)
                    g_cand[row0 * CAP + pos] = make_int2(kbase + BT, __float_as_int(d10));
            }
            if (d11 < 0.f) {
                int pos = atomicAdd(&g_cnt[row1], 1);
                if (pos < CAP)
                    g_cand[row1 * CAP + pos] = make_int2(kbase + BT, __float_as_int(d11));
            }
        }
    }
}

// ---------------- pass 3: per-row finalize, block-reduced scalars -------------
// note: stored d's are shifted by -cut[row] (row-uniform) -> differences exact
// grid 1024 x 256 thr, 8 rows per block (grid exact: no early return)
__global__ void k_finalize(const float* __restrict__ z,
                           const float* __restrict__ cb,
                           float* __restrict__ out) {
    __shared__ float s_mse[8], s_H[8];
    __shared__ float s_idx[8];

    int tid  = threadIdx.x;
    int wid  = tid >> 5;
    int lane = tid & 31;
    int gw   = blockIdx.x * 8 + wid;               // row for this warp

    int cnt = min(g_cnt[gw], CAP);

    float dmin = 1e30f, S1 = 0.f, S2 = 0.f;
    int   idx  = 0x7fffffff;
    for (int i = lane; i < cnt; i += 32) {
        int2 c = g_cand[gw * CAP + i];
        float d = __int_as_float(c.y);
        if (d < dmin) {
            float delta = -100.f * (dmin - d);
            float sc = __expf(delta);
            S2 = sc * (S2 + delta * S1);
            S1 = sc * S1 + 1.f;
            dmin = d; idx = c.x;
        } else {
            float arg = -100.f * (d - dmin);
            float e = __expf(arg);
            S1 += e; S2 += e * arg;
            if (d == dmin) idx = min(idx, c.x);
        }
    }
    for (int o = 16; o; o >>= 1) {
        float od  = __shfl_xor_sync(0xffffffffu, dmin, o);
        float oS1 = __shfl_xor_sync(0xffffffffu, S1, o);
        float oS2 = __shfl_xor_sync(0xffffffffu, S2, o);
        int   oix = __shfl_xor_sync(0xffffffffu, idx, o);
        float dlo = fminf(dmin, od);
        float da = -100.f * (dmin - dlo); float sa = __expf(da);
        float db = -100.f * (od  - dlo);  float sb = __expf(db);
        float nS2 = sa * (S2 + da * S1) + sb * (oS2 + db * oS1);
        float nS1 = sa * S1 + sb * oS1;
        int nidx;
        if (od < dmin)       nidx = oix;
        else if (od == dmin) nidx = min(idx, oix);
        else                 nidx = idx;
        dmin = dlo; S1 = nS1; S2 = nS2; idx = nidx;
    }

    float inv = 1.0f / (S1 * 8192.0f);
    for (int i = lane; i < cnt; i += 32) {
        int2 c = g_cand[gw * CAP + i];
        float e = __expf(-100.f * (__int_as_float(c.y) - dmin));
        if (e > 0.f) atomicAdd(&g_avg[c.x], e * inv);
    }

    int b = gw >> 8, rem = gw & 255;
    float local = 0.f;
    if (lane < 8) {
        float q  = cb[idx * 8 + lane];
        float zv = z[b * 2048 + lane * 256 + rem];
        out[b * 2048 + lane * 256 + rem] = q;       // z_q (straight-through fwd)
        float df = q - zv;
        local = df * df;
    }
    local += __shfl_xor_sync(0xffffffffu, local, 1);
    local += __shfl_xor_sync(0xffffffffu, local, 2);
    local += __shfl_xor_sync(0xffffffffu, local, 4);
    if (lane == 0) {
        s_mse[wid] = local;
        s_H[wid]   = S2 / S1 - logf(S1);           // = sum p*logp for this row
        s_idx[wid] = (float)idx;
    }
    __syncthreads();
    if (tid < 8)                                    // coalesced idx write (32B)
        out[65537 + blockIdx.x * 8 + tid] = s_idx[tid];
    if (tid == 0) {
        float m = 0.f, h = 0.f;
#pragma unroll
        for (int i = 0; i < 8; i++) { m += s_mse[i]; h += s_H[i]; }
        atomicAdd(&g_mse, m);                       // 1024 atomics, not 8192
        atomicAdd(&g_sampleH, h);
    }
}

// ---------------- pass 4: avg-entropy reduce + loss ---------------------------
__global__ void k_final(float* __restrict__ out) {
    __shared__ float red[256];
    float a = 0.f;
    for (int k = threadIdx.x; k < K_CODES; k += 256) {
        float av = g_avg[k];
        a += av * logf(av + 1e-5f);
    }
    red[threadIdx.x] = a;
    __syncthreads();
    for (int s = 128; s; s >>= 1) {
        if (threadIdx.x < s) red[threadIdx.x] += red[threadIdx.x + s];
        __syncthreads();
    }
    if (threadIdx.x == 0) {
        float sample_entropy = -(g_sampleH / 8192.0f);
        float ent = 0.1f * (sample_entropy + red[0]);
        out[65536] = 1.25f * g_mse / 65536.0f + ent;
    }
}

// ---------------- launch ------------------------------------------------------
extern "C" void kernel_launch(void* const* d_in, const int* in_sizes, int n_in,
                              void* d_out, int out_size) {
    const float* z  = (const float*)d_in[0];
    const float* cb = (const float*)d_in[1];
    float* out = (float*)d_out;
    (void)in_sizes; (void)n_in; (void)out_size;

    k_init<<<64, 256>>>(cb);
    k_warm<<<128, 256>>>(z);
    k_nop<<<1, 32>>>();                       // keeps k_sweep as ncu's profiled launch
    k_sweep<<<dim3(K_CODES / CPB, RSPLIT), BT>>>(z);
    k_finalize<<<1024, 256>>>(z, cb, out);
    k_final<<<1, 256>>>(out);
}